// round 10
// baseline (speedup 1.0000x reference)
#include <cuda_runtime.h>

// Problem constants (B=2, S=2048, D=1024, H=16, hd=64)
#define Bb 2
#define Ss 2048
#define Dd 1024
#define Hh 16
#define HD 64
#define BH (Bb*Hh)          // 32
#define MTOK (Bb*Ss)        // 4096

// ---------------- scratch (device globals; referenced ONLY from device code) --
__device__ float g_kproj[Bb*Ss*Dd];
__device__ float g_vproj[Bb*Ss*Dd];
__device__ float g_qrope[Bb*Ss*Dd];
__device__ float g_rcolsum[BH*Ss];
__device__ float g_attout[Bb*Ss*Dd];

// ---------------- tf32 mma + cp.async helpers --------------------------------
__device__ __forceinline__ unsigned f2tf(float x){
    unsigned u; asm("cvt.rna.tf32.f32 %0, %1;" : "=r"(u) : "f"(x)); return u;
}
__device__ __forceinline__ void mma8(float* c, const unsigned* a, const unsigned* b){
    asm volatile("mma.sync.aligned.m16n8k8.row.col.f32.tf32.tf32.f32 "
        "{%0,%1,%2,%3}, {%4,%5,%6,%7}, {%8,%9}, {%0,%1,%2,%3};"
        : "+f"(c[0]),"+f"(c[1]),"+f"(c[2]),"+f"(c[3])
        : "r"(a[0]),"r"(a[1]),"r"(a[2]),"r"(a[3]),"r"(b[0]),"r"(b[1]));
}
__device__ __forceinline__ void cp16(void* dst, const void* src){
    unsigned d = (unsigned)__cvta_generic_to_shared(dst);
    asm volatile("cp.async.cg.shared.global [%0], [%1], 16;" :: "r"(d), "l"(src));
}
#define CP_COMMIT() asm volatile("cp.async.commit_group;")
#define CP_WAIT1()  asm volatile("cp.async.wait_group 1;")
#define CP_WAIT0()  asm volatile("cp.async.wait_group 0;")

// stride-16 XOR swizzle (16B granularity): float index for logical (row, k)
__device__ __forceinline__ int swz16(int r, int k){
    return (r << 4) + ((((k >> 2) ^ r) & 3) << 2) + (k & 3);
}

// ---------------- big GEMM: C = A @ W^T + bias  (M=4096, N=K=1024) ------------
// BK=16, 3-stage cp.async, stride-16 swizzled fp32 smem, single sync per iter.
template<int DST, int GATHER>
__global__ void __launch_bounds__(256)
gemm_tc(const float* __restrict__ A, const float* __restrict__ W,
        const float* __restrict__ bias, float* __restrict__ Cout)
{
    __shared__ float As[3][128*16];
    __shared__ float Bs[3][128*16];
    float* Cg = (DST==0) ? g_kproj : (DST==1) ? g_vproj : Cout;
    const int tid = threadIdx.x;
    const int lane = tid & 31, wid = tid >> 5;
    const int wm = (wid & 1) * 64, wn = (wid >> 1) * 32;
    const int gid = lane >> 2, tig = lane & 3;
    const int bm = blockIdx.y * 128, bn = blockIdx.x * 128;

    auto issue = [&](int s, int k0){
        #pragma unroll
        for (int l = 0; l < 2; l++) {
            int id = tid + l*256;
            int m = id >> 2, kc4 = id & 3;          // row, 4-float chunk
            int doff = (m << 4) + (((kc4 ^ m) & 3) << 2);
            const float* srcA;
            if (GATHER) {
                int m2 = bm + m, b = m2 >> 11, sq = m2 & (Ss-1);
                int k = k0 + kc4*4, h = k >> 6, i = k & 63;
                srcA = g_attout + ((((size_t)(b*Hh + h)) * Ss + sq) << 6) + i;
            } else {
                srcA = A + (size_t)(bm + m) * Dd + k0 + kc4*4;
            }
            cp16(&As[s][doff], srcA);
            cp16(&Bs[s][doff], W + (size_t)(bn + m) * Dd + k0 + kc4*4);
        }
    };
    issue(0, 0);  CP_COMMIT();
    issue(1, 16); CP_COMMIT();

    float acc[4][4][4];
    #pragma unroll
    for (int a = 0; a < 4; a++)
        #pragma unroll
        for (int b = 0; b < 4; b++)
            #pragma unroll
            for (int c = 0; c < 4; c++) acc[a][b][c] = 0.f;

    for (int it = 0; it < 64; it++) {
        if (it < 63) { CP_WAIT1(); } else { CP_WAIT0(); }
        __syncthreads();
        const int s = it % 3;
        #pragma unroll
        for (int ks = 0; ks < 16; ks += 8) {
            unsigned af[4][4], bf[4][2];
            #pragma unroll
            for (int mt = 0; mt < 4; mt++) {
                int r = wm + mt*16 + gid;
                af[mt][0] = f2tf(As[s][swz16(r,     ks + tig    )]);
                af[mt][1] = f2tf(As[s][swz16(r + 8, ks + tig    )]);
                af[mt][2] = f2tf(As[s][swz16(r,     ks + tig + 4)]);
                af[mt][3] = f2tf(As[s][swz16(r + 8, ks + tig + 4)]);
            }
            #pragma unroll
            for (int nt = 0; nt < 4; nt++) {
                int cN = wn + nt*8 + gid;
                bf[nt][0] = f2tf(Bs[s][swz16(cN, ks + tig    )]);
                bf[nt][1] = f2tf(Bs[s][swz16(cN, ks + tig + 4)]);
            }
            #pragma unroll
            for (int mt = 0; mt < 4; mt++)
                #pragma unroll
                for (int nt = 0; nt < 4; nt++)
                    mma8(acc[mt][nt], af[mt], bf[nt]);
        }
        if (it + 2 < 64) { issue((it + 2) % 3, (it + 2) * 16); CP_COMMIT(); }
    }
    #pragma unroll
    for (int mt = 0; mt < 4; mt++) {
        int r0 = bm + wm + mt*16 + gid;
        #pragma unroll
        for (int nt = 0; nt < 4; nt++) {
            int c0 = bn + wn + nt*8 + 2*tig;
            float b0v = bias[c0], b1v = bias[c0+1];
            Cg[(size_t)r0*Dd + c0]       = acc[mt][nt][0] + b0v;
            Cg[(size_t)r0*Dd + c0+1]     = acc[mt][nt][1] + b1v;
            Cg[(size_t)(r0+8)*Dd + c0]   = acc[mt][nt][2] + b0v;
            Cg[(size_t)(r0+8)*Dd + c0+1] = acc[mt][nt][3] + b1v;
        }
    }
}

// ---------------- RoPE (intrinsics only; no local-memory pool) ----------------
template<int MODE>
__global__ void __launch_bounds__(256)
rope_kernel(const float* __restrict__ xq, const int* __restrict__ pos)
{
    const float* x = (MODE == 0) ? xq : (MODE == 1 ? (const float*)g_kproj
                                                   : (const float*)g_vproj);
    float* y = (MODE == 0) ? g_qrope : (MODE == 1 ? g_kproj : g_vproj);
    int t = blockIdx.x * blockDim.x + threadIdx.x;
    if (t >= Bb*Ss*Dd/2) return;
    int i   = t & 31;
    int vec = t >> 5;
    int s2  = vec & (Ss - 1);
    float p = (float)pos[s2];
    float invf = exp2f(-(float)i * 0.41524101186092033f);
    float ang = p * invf;
    float k = rintf(ang * 0.15915494309189535f);
    float r = fmaf(-k, 6.28318548202514648f, ang);
    r = fmaf(k, 1.7484556e-7f, r);
    float c = __cosf(r);
    float s = __sinf(r);
    size_t base = (size_t)vec * HD + i;
    float x1 = x[base], x2 = x[base + 32];
    y[base]      = x1 * c - x2 * s;
    y[base + 32] = x2 * c + x1 * s;
}

// ---------------- colsum: 512 threads, warps 4(q) x 4(k), K frags in regs -----
__global__ void __launch_bounds__(512)
colsum_kernel()
{
    __shared__ float Qs[2][64*68];      // stage 1 doubles as K staging at start
    __shared__ float cpart[4][64];
    const int bh = blockIdx.y;
    const int bk = blockIdx.x * 64;
    const int tid = threadIdx.x;
    const int lane = tid & 31, wid = tid >> 5;
    const int wm = wid & 3, wn = wid >> 2;      // 4(q) x 4(k)
    const int gid = lane >> 2, tig = lane & 3;
    const float* Kp = g_kproj + (((size_t)bh * Ss + bk) << 6);
    const float* Qp = g_qrope + ((size_t)bh * Ss << 6);

    auto issueQ = [&](int s, int q0){
        #pragma unroll
        for (int l = 0; l < 2; l++) {
            int id = tid + l*512;
            int r = id >> 4, kc = (id & 15) << 2;
            cp16(&Qs[s][r*68 + kc], Qp + ((size_t)(q0 + r) << 6) + kc);
        }
    };
    #pragma unroll
    for (int l = 0; l < 2; l++) {
        int id = tid + l*512;
        int r = id >> 4, kc = (id & 15) << 2;
        cp16(&Qs[1][r*68 + kc], Kp + ((size_t)r << 6) + kc);
    }
    CP_COMMIT();
    issueQ(0, 0); CP_COMMIT();
    CP_WAIT1();
    __syncthreads();
    unsigned bfa[8][2][2];              // persistent K fragments (16 cols/warp)
    #pragma unroll
    for (int ks8 = 0; ks8 < 8; ks8++)
        #pragma unroll
        for (int nt = 0; nt < 2; nt++) {
            int rk = wn*16 + nt*8 + gid;
            bfa[ks8][nt][0] = f2tf(Qs[1][rk*68 + ks8*8 + tig    ]);
            bfa[ks8][nt][1] = f2tf(Qs[1][rk*68 + ks8*8 + tig + 4]);
        }
    __syncthreads();
    issueQ(1, 64); CP_COMMIT();

    float cs[2][2];
    #pragma unroll
    for (int nt = 0; nt < 2; nt++) { cs[nt][0] = 0.f; cs[nt][1] = 0.f; }

    for (int it = 0; it < 32; it++) {
        if (it + 1 < 32) { CP_WAIT1(); } else { CP_WAIT0(); }
        __syncthreads();
        const int s = it & 1;
        float sacc[2][4];
        #pragma unroll
        for (int nt = 0; nt < 2; nt++)
            #pragma unroll
            for (int c = 0; c < 4; c++) sacc[nt][c] = 0.f;
        #pragma unroll
        for (int ks8 = 0; ks8 < 8; ks8++) {
            unsigned aq[4];
            int rq = wm*16 + gid;
            aq[0] = f2tf(Qs[s][ rq     *68 + ks8*8 + tig    ]);
            aq[1] = f2tf(Qs[s][(rq + 8)*68 + ks8*8 + tig    ]);
            aq[2] = f2tf(Qs[s][ rq     *68 + ks8*8 + tig + 4]);
            aq[3] = f2tf(Qs[s][(rq + 8)*68 + ks8*8 + tig + 4]);
            mma8(sacc[0], aq, bfa[ks8][0]);
            mma8(sacc[1], aq, bfa[ks8][1]);
        }
        int gq0 = it*64 + wm*16 + gid;
        #pragma unroll
        for (int nt = 0; nt < 2; nt++) {
            int gk0 = bk + wn*16 + nt*8 + 2*tig;
            float e0 = (gq0   == gk0  ) ? 1.f : __expf(sacc[nt][0]*0.125f);
            float e1 = (gq0   == gk0+1) ? 1.f : __expf(sacc[nt][1]*0.125f);
            float e2 = (gq0+8 == gk0  ) ? 1.f : __expf(sacc[nt][2]*0.125f);
            float e3 = (gq0+8 == gk0+1) ? 1.f : __expf(sacc[nt][3]*0.125f);
            cs[nt][0] += e0 + e2;
            cs[nt][1] += e1 + e3;
        }
        __syncthreads();
        if (it + 2 < 32) issueQ(s, (it + 2) * 64);
        CP_COMMIT();
    }
    // reduce over the 8 row-groups within each warp
    #pragma unroll
    for (int nt = 0; nt < 2; nt++)
        #pragma unroll
        for (int j = 0; j < 2; j++) {
            cs[nt][j] += __shfl_xor_sync(0xffffffffu, cs[nt][j], 4);
            cs[nt][j] += __shfl_xor_sync(0xffffffffu, cs[nt][j], 8);
            cs[nt][j] += __shfl_xor_sync(0xffffffffu, cs[nt][j], 16);
        }
    if (gid == 0) {
        #pragma unroll
        for (int nt = 0; nt < 2; nt++) {
            cpart[wm][wn*16 + nt*8 + 2*tig    ] = cs[nt][0];
            cpart[wm][wn*16 + nt*8 + 2*tig + 1] = cs[nt][1];
        }
    }
    __syncthreads();
    if (tid < 64) {
        float s = cpart[0][tid] + cpart[1][tid] + cpart[2][tid] + cpart[3][tid];
        g_rcolsum[bh * Ss + bk + tid] = 1.0f / s;
    }
}

// ---------------- V' = r * V (fold softmax normalizer into V once) -----------
__global__ void __launch_bounds__(256)
vscale_kernel()
{
    int idx = blockIdx.x * 256 + threadIdx.x;     // float4 index
    float4* vp = (float4*)g_vproj;
    int row = idx >> 4;
    float r = g_rcolsum[row];
    float4 v = vp[idx];
    v.x *= r; v.y *= r; v.z *= r; v.w *= r;
    vp[idx] = v;
}

// ---------------- fused attention: 128q block, E stays in registers ----------
#define KST 76
#define VST 72
#define VOFF (32*KST)
#define STG  (32*KST + 32*VST)
__global__ void __launch_bounds__(256)
attn_kernel()
{
    __shared__ float KV[2][STG];
    const int bh = blockIdx.y;
    const int bq = blockIdx.x * 128;
    const int tid = threadIdx.x;
    const int lane = tid & 31, wid = tid >> 5;
    const int gid = lane >> 2, tig = lane & 3;
    const float* Qp = g_qrope + (((size_t)bh * Ss + bq) << 6);
    const float* Kp = g_kproj + ((size_t)bh * Ss << 6);
    const float* Vp = g_vproj + ((size_t)bh * Ss << 6);

    auto issueKV = [&](int s, int k0){
        #pragma unroll
        for (int l = 0; l < 4; l++) {
            int id = tid + l*256;
            int r = id >> 4, kc = (id & 15) << 2;
            if (r < 32)
                cp16(&KV[s][r*KST + kc], Kp + ((size_t)(k0 + r) << 6) + kc);
            else
                cp16(&KV[s][VOFF + (r-32)*VST + kc], Vp + ((size_t)(k0 + r - 32) << 6) + kc);
        }
    };

    float* Qst = &KV[0][0];
    #pragma unroll
    for (int l = 0; l < 8; l++) {
        int id = tid + l*256;
        int r = id >> 4, kc = (id & 15) << 2;
        cp16(&Qst[r*72 + kc], Qp + ((size_t)r << 6) + kc);
    }
    CP_COMMIT();
    CP_WAIT0();
    __syncthreads();
    const int rq = wid*16 + gid;
    unsigned aq[8][4];
    #pragma unroll
    for (int ks8 = 0; ks8 < 8; ks8++) {
        aq[ks8][0] = f2tf(Qst[ rq     *72 + ks8*8 + tig    ]);
        aq[ks8][1] = f2tf(Qst[(rq + 8)*72 + ks8*8 + tig    ]);
        aq[ks8][2] = f2tf(Qst[ rq     *72 + ks8*8 + tig + 4]);
        aq[ks8][3] = f2tf(Qst[(rq + 8)*72 + ks8*8 + tig + 4]);
    }
    __syncthreads();
    issueKV(0, 0);  CP_COMMIT();
    issueKV(1, 32); CP_COMMIT();

    float oacc[8][4];
    #pragma unroll
    for (int nt = 0; nt < 8; nt++)
        #pragma unroll
        for (int c = 0; c < 4; c++) oacc[nt][c] = 0.f;

    const int src0 = (lane & 0x1C) | (tig >> 1);
    const int src1 = src0 + 2;
    const bool podd = (tig & 1);

    for (int it = 0; it < 64; it++) {
        if (it + 1 < 64) { CP_WAIT1(); } else { CP_WAIT0(); }
        __syncthreads();
        const int s = it & 1;
        float sacc[4][4];
        #pragma unroll
        for (int nt = 0; nt < 4; nt++)
            #pragma unroll
            for (int c = 0; c < 4; c++) sacc[nt][c] = 0.f;
        #pragma unroll
        for (int ks8 = 0; ks8 < 8; ks8++) {
            unsigned bf[4][2];
            #pragma unroll
            for (int nt = 0; nt < 4; nt++) {
                int rk = nt*8 + gid;
                bf[nt][0] = f2tf(KV[s][rk*KST + ks8*8 + tig    ]);
                bf[nt][1] = f2tf(KV[s][rk*KST + ks8*8 + tig + 4]);
            }
            #pragma unroll
            for (int nt = 0; nt < 4; nt++) mma8(sacc[nt], aq[ks8], bf[nt]);
        }
        {
            int gq = bq + rq;
            #pragma unroll
            for (int nt = 0; nt < 4; nt++) {
                int gk = it*32 + nt*8 + 2*tig;
                sacc[nt][0] = (gq   == gk  ) ? 1.f : __expf(sacc[nt][0]*0.125f);
                sacc[nt][1] = (gq   == gk+1) ? 1.f : __expf(sacc[nt][1]*0.125f);
                sacc[nt][2] = (gq+8 == gk  ) ? 1.f : __expf(sacc[nt][2]*0.125f);
                sacc[nt][3] = (gq+8 == gk+1) ? 1.f : __expf(sacc[nt][3]*0.125f);
            }
        }
        const float* Vb = &KV[s][VOFF];
        #pragma unroll
        for (int ks8 = 0; ks8 < 4; ks8++) {
            float va = __shfl_sync(0xffffffffu, sacc[ks8][0], src0);
            float vb = __shfl_sync(0xffffffffu, sacc[ks8][1], src0);
            float vc = __shfl_sync(0xffffffffu, sacc[ks8][2], src0);
            float vd = __shfl_sync(0xffffffffu, sacc[ks8][3], src0);
            float wa = __shfl_sync(0xffffffffu, sacc[ks8][0], src1);
            float wb = __shfl_sync(0xffffffffu, sacc[ks8][1], src1);
            float wc = __shfl_sync(0xffffffffu, sacc[ks8][2], src1);
            float wd = __shfl_sync(0xffffffffu, sacc[ks8][3], src1);
            unsigned ae[4];
            ae[0] = f2tf(podd ? vb : va);
            ae[1] = f2tf(podd ? vd : vc);
            ae[2] = f2tf(podd ? wb : wa);
            ae[3] = f2tf(podd ? wd : wc);
            int kr0 = ks8*8 + tig, kr1 = kr0 + 4;
            #pragma unroll
            for (int nt = 0; nt < 8; nt++) {
                unsigned bv[2];
                int cd = nt*8 + gid;
                bv[0] = f2tf(Vb[kr0*VST + cd]);
                bv[1] = f2tf(Vb[kr1*VST + cd]);
                mma8(oacc[nt], ae, bv);
            }
        }
        __syncthreads();
        if (it + 2 < 64) issueKV(s, (it + 2) * 32);
        CP_COMMIT();
    }
    {
        int gq = bq + rq;
        float* O0 = g_attout + (((size_t)bh * Ss + gq) << 6);
        float* O1 = O0 + ((size_t)8 << 6);
        #pragma unroll
        for (int nt = 0; nt < 8; nt++) {
            int d = nt*8 + 2*tig;
            *(float2*)(O0 + d) = make_float2(oacc[nt][0], oacc[nt][1]);
            *(float2*)(O1 + d) = make_float2(oacc[nt][2], oacc[nt][3]);
        }
    }
}

// ---------------- launch (pure kernel launches; graph-capturable) -------------
extern "C" void kernel_launch(void* const* d_in, const int* in_sizes, int n_in,
                              void* d_out, int out_size)
{
    const float* query = (const float*)d_in[0];
    const float* key_  = (const float*)d_in[1];
    const float* value = (const float*)d_in[2];
    const int*   pos   = (const int*)  d_in[3];
    const float* Wk = (const float*)d_in[4];
    const float* bk = (const float*)d_in[5];
    const float* Wv = (const float*)d_in[6];
    const float* bv = (const float*)d_in[7];
    const float* Wo = (const float*)d_in[8];
    const float* bo = (const float*)d_in[9];
    float* out = (float*)d_out;

    dim3 blk(256);
    dim3 ggrid(Dd/128, MTOK/128);     // 8 x 32

    gemm_tc<0,0><<<ggrid, blk>>>(key_,  Wk, bk, nullptr);
    gemm_tc<1,0><<<ggrid, blk>>>(value, Wv, bv, nullptr);

    int pairs = Bb*Ss*Dd/2;
    rope_kernel<0><<<(pairs + 255)/256, 256>>>(query, pos);
    rope_kernel<1><<<(pairs + 255)/256, 256>>>(query, pos);
    rope_kernel<2><<<(pairs + 255)/256, 256>>>(query, pos);

    colsum_kernel<<<dim3(Ss/64, BH), dim3(512)>>>();
    vscale_kernel<<<(Bb*Ss*Dd/4)/256, blk>>>();
    attn_kernel<<<dim3(Ss/128, BH), blk>>>();

    gemm_tc<2,1><<<ggrid, blk>>>(nullptr, Wo, bo, out);
}

// round 13
// speedup vs baseline: 1.0560x; 1.0560x over previous
#include <cuda_runtime.h>

// Problem constants (B=2, S=2048, D=1024, H=16, hd=64)
#define Bb 2
#define Ss 2048
#define Dd 1024
#define Hh 16
#define HD 64
#define BH (Bb*Hh)          // 32
#define MTOK (Bb*Ss)        // 4096

// ---------------- scratch (device globals; referenced ONLY from device code) --
__device__ float g_kproj[Bb*Ss*Dd];
__device__ float g_vproj[Bb*Ss*Dd];
__device__ float g_qrope[Bb*Ss*Dd];
__device__ float g_rcolsum[BH*Ss];
__device__ float g_attout[Bb*Ss*Dd];

// ---------------- tf32 mma + cp.async helpers --------------------------------
__device__ __forceinline__ unsigned f2tf(float x){
    unsigned u; asm("cvt.rna.tf32.f32 %0, %1;" : "=r"(u) : "f"(x)); return u;
}
__device__ __forceinline__ void mma8(float* c, const unsigned* a, const unsigned* b){
    asm volatile("mma.sync.aligned.m16n8k8.row.col.f32.tf32.tf32.f32 "
        "{%0,%1,%2,%3}, {%4,%5,%6,%7}, {%8,%9}, {%0,%1,%2,%3};"
        : "+f"(c[0]),"+f"(c[1]),"+f"(c[2]),"+f"(c[3])
        : "r"(a[0]),"r"(a[1]),"r"(a[2]),"r"(a[3]),"r"(b[0]),"r"(b[1]));
}
__device__ __forceinline__ void cp16(void* dst, const void* src){
    unsigned d = (unsigned)__cvta_generic_to_shared(dst);
    asm volatile("cp.async.cg.shared.global [%0], [%1], 16;" :: "r"(d), "l"(src));
}
#define CP_COMMIT() asm volatile("cp.async.commit_group;")
#define CP_WAIT1()  asm volatile("cp.async.wait_group 1;")
#define CP_WAIT0()  asm volatile("cp.async.wait_group 0;")

// stride-16 swizzle keyed on (r>>1): bank = 16*(r&1) + 4*(((k>>2)^(r>>1))&3) + (k&3)
// -> 8 consecutive rows at fixed k-chunk hit 8 distinct bank groups (conflict-free).
__device__ __forceinline__ int swz16(int r, int k){
    return (r << 4) + ((((k >> 2) ^ (r >> 1)) & 3) << 2) + (k & 3);
}

// ---------------- big GEMM: C = A @ W^T + bias  (M=4096, N=K=1024) ------------
// BK=16, 3-stage cp.async, conflict-free stride-16 swizzle, 48KB static smem,
// single __syncthreads per k-iteration.
template<int DST, int GATHER>
__global__ void __launch_bounds__(256)
gemm_tc(const float* __restrict__ A, const float* __restrict__ W,
        const float* __restrict__ bias, float* __restrict__ Cout)
{
    __shared__ float As[3][128*16];
    __shared__ float Bs[3][128*16];
    float* Cg = (DST==0) ? g_kproj : (DST==1) ? g_vproj : Cout;
    const int tid = threadIdx.x;
    const int lane = tid & 31, wid = tid >> 5;
    const int wm = (wid & 1) * 64, wn = (wid >> 1) * 32;
    const int gid = lane >> 2, tig = lane & 3;
    const int bm = blockIdx.y * 128, bn = blockIdx.x * 128;

    auto issue = [&](int s, int k0){
        #pragma unroll
        for (int l = 0; l < 2; l++) {
            int id = tid + l*256;
            int m = id >> 2, kc4 = id & 3;          // row, 4-float chunk
            int doff = (m << 4) + (((kc4 ^ (m >> 1)) & 3) << 2);
            const float* srcA;
            if (GATHER) {
                int m2 = bm + m, b = m2 >> 11, sq = m2 & (Ss-1);
                int k = k0 + kc4*4, h = k >> 6, i = k & 63;
                srcA = g_attout + ((((size_t)(b*Hh + h)) * Ss + sq) << 6) + i;
            } else {
                srcA = A + (size_t)(bm + m) * Dd + k0 + kc4*4;
            }
            cp16(&As[s][doff], srcA);
            cp16(&Bs[s][doff], W + (size_t)(bn + m) * Dd + k0 + kc4*4);
        }
    };
    issue(0, 0);  CP_COMMIT();
    issue(1, 16); CP_COMMIT();

    float acc[4][4][4];
    #pragma unroll
    for (int a = 0; a < 4; a++)
        #pragma unroll
        for (int b = 0; b < 4; b++)
            #pragma unroll
            for (int c = 0; c < 4; c++) acc[a][b][c] = 0.f;

    for (int it = 0; it < 64; it++) {
        if (it < 63) { CP_WAIT1(); } else { CP_WAIT0(); }
        __syncthreads();
        const int s = it % 3;
        #pragma unroll
        for (int ks = 0; ks < 16; ks += 8) {
            unsigned af[4][4], bf[4][2];
            #pragma unroll
            for (int mt = 0; mt < 4; mt++) {
                int r = wm + mt*16 + gid;
                af[mt][0] = f2tf(As[s][swz16(r,     ks + tig    )]);
                af[mt][1] = f2tf(As[s][swz16(r + 8, ks + tig    )]);
                af[mt][2] = f2tf(As[s][swz16(r,     ks + tig + 4)]);
                af[mt][3] = f2tf(As[s][swz16(r + 8, ks + tig + 4)]);
            }
            #pragma unroll
            for (int nt = 0; nt < 4; nt++) {
                int cN = wn + nt*8 + gid;
                bf[nt][0] = f2tf(Bs[s][swz16(cN, ks + tig    )]);
                bf[nt][1] = f2tf(Bs[s][swz16(cN, ks + tig + 4)]);
            }
            #pragma unroll
            for (int mt = 0; mt < 4; mt++)
                #pragma unroll
                for (int nt = 0; nt < 4; nt++)
                    mma8(acc[mt][nt], af[mt], bf[nt]);
        }
        if (it + 2 < 64) { issue((it + 2) % 3, (it + 2) * 16); CP_COMMIT(); }
    }
    #pragma unroll
    for (int mt = 0; mt < 4; mt++) {
        int r0 = bm + wm + mt*16 + gid;
        #pragma unroll
        for (int nt = 0; nt < 4; nt++) {
            int c0 = bn + wn + nt*8 + 2*tig;
            float b0v = bias[c0], b1v = bias[c0+1];
            Cg[(size_t)r0*Dd + c0]       = acc[mt][nt][0] + b0v;
            Cg[(size_t)r0*Dd + c0+1]     = acc[mt][nt][1] + b1v;
            Cg[(size_t)(r0+8)*Dd + c0]   = acc[mt][nt][2] + b0v;
            Cg[(size_t)(r0+8)*Dd + c0+1] = acc[mt][nt][3] + b1v;
        }
    }
}

// ---------------- RoPE (intrinsics only; no local-memory pool) ----------------
template<int MODE>
__global__ void __launch_bounds__(256)
rope_kernel(const float* __restrict__ xq, const int* __restrict__ pos)
{
    const float* x = (MODE == 0) ? xq : (MODE == 1 ? (const float*)g_kproj
                                                   : (const float*)g_vproj);
    float* y = (MODE == 0) ? g_qrope : (MODE == 1 ? g_kproj : g_vproj);
    int t = blockIdx.x * blockDim.x + threadIdx.x;
    if (t >= Bb*Ss*Dd/2) return;
    int i   = t & 31;
    int vec = t >> 5;
    int s2  = vec & (Ss - 1);
    float p = (float)pos[s2];
    float invf = exp2f(-(float)i * 0.41524101186092033f);
    float ang = p * invf;
    float k = rintf(ang * 0.15915494309189535f);
    float r = fmaf(-k, 6.28318548202514648f, ang);
    r = fmaf(k, 1.7484556e-7f, r);
    float c = __cosf(r);
    float s = __sinf(r);
    size_t base = (size_t)vec * HD + i;
    float x1 = x[base], x2 = x[base + 32];
    y[base]      = x1 * c - x2 * s;
    y[base + 32] = x2 * c + x1 * s;
}

// ---------------- colsum: 64 k-cols per block, K frags in registers ----------
__global__ void __launch_bounds__(256)
colsum_kernel()
{
    __shared__ float Qs[2][64*68];
    __shared__ float cpart[4][64];
    const int bh = blockIdx.y;
    const int bk = blockIdx.x * 64;
    const int tid = threadIdx.x;
    const int lane = tid & 31, wid = tid >> 5;
    const int wm = wid & 3, wn = wid >> 2;
    const int gid = lane >> 2, tig = lane & 3;
    const float* Kp = g_kproj + (((size_t)bh * Ss + bk) << 6);
    const float* Qp = g_qrope + ((size_t)bh * Ss << 6);

    auto issueQ = [&](int s, int q0){
        #pragma unroll
        for (int l = 0; l < 4; l++) {
            int id = tid + l*256;
            int r = id >> 4, kc = (id & 15) << 2;
            cp16(&Qs[s][r*68 + kc], Qp + ((size_t)(q0 + r) << 6) + kc);
        }
    };
    #pragma unroll
    for (int l = 0; l < 4; l++) {
        int id = tid + l*256;
        int r = id >> 4, kc = (id & 15) << 2;
        cp16(&Qs[1][r*68 + kc], Kp + ((size_t)r << 6) + kc);
    }
    CP_COMMIT();
    issueQ(0, 0); CP_COMMIT();
    CP_WAIT1();
    __syncthreads();
    unsigned bfa[8][4][2];
    #pragma unroll
    for (int ks8 = 0; ks8 < 8; ks8++)
        #pragma unroll
        for (int nt = 0; nt < 4; nt++) {
            int rk = wn*32 + nt*8 + gid;
            bfa[ks8][nt][0] = f2tf(Qs[1][rk*68 + ks8*8 + tig    ]);
            bfa[ks8][nt][1] = f2tf(Qs[1][rk*68 + ks8*8 + tig + 4]);
        }
    __syncthreads();
    issueQ(1, 64); CP_COMMIT();

    float cs[4][2];
    #pragma unroll
    for (int nt = 0; nt < 4; nt++) { cs[nt][0] = 0.f; cs[nt][1] = 0.f; }

    for (int it = 0; it < 32; it++) {
        if (it + 1 < 32) { CP_WAIT1(); } else { CP_WAIT0(); }
        __syncthreads();
        const int s = it & 1;
        float sacc[4][4];
        #pragma unroll
        for (int nt = 0; nt < 4; nt++)
            #pragma unroll
            for (int c = 0; c < 4; c++) sacc[nt][c] = 0.f;
        #pragma unroll
        for (int ks8 = 0; ks8 < 8; ks8++) {
            unsigned aq[4];
            int rq = wm*16 + gid;
            aq[0] = f2tf(Qs[s][ rq     *68 + ks8*8 + tig    ]);
            aq[1] = f2tf(Qs[s][(rq + 8)*68 + ks8*8 + tig    ]);
            aq[2] = f2tf(Qs[s][ rq     *68 + ks8*8 + tig + 4]);
            aq[3] = f2tf(Qs[s][(rq + 8)*68 + ks8*8 + tig + 4]);
            #pragma unroll
            for (int nt = 0; nt < 4; nt++) mma8(sacc[nt], aq, bfa[ks8][nt]);
        }
        int gq0 = it*64 + wm*16 + gid;
        #pragma unroll
        for (int nt = 0; nt < 4; nt++) {
            int gk0 = bk + wn*32 + nt*8 + 2*tig;
            float e0 = (gq0   == gk0  ) ? 1.f : __expf(sacc[nt][0]*0.125f);
            float e1 = (gq0   == gk0+1) ? 1.f : __expf(sacc[nt][1]*0.125f);
            float e2 = (gq0+8 == gk0  ) ? 1.f : __expf(sacc[nt][2]*0.125f);
            float e3 = (gq0+8 == gk0+1) ? 1.f : __expf(sacc[nt][3]*0.125f);
            cs[nt][0] += e0 + e2;
            cs[nt][1] += e1 + e3;
        }
        __syncthreads();
        if (it + 2 < 32) issueQ(s, (it + 2) * 64);
        CP_COMMIT();
    }
    #pragma unroll
    for (int nt = 0; nt < 4; nt++)
        #pragma unroll
        for (int j = 0; j < 2; j++) {
            cs[nt][j] += __shfl_xor_sync(0xffffffffu, cs[nt][j], 4);
            cs[nt][j] += __shfl_xor_sync(0xffffffffu, cs[nt][j], 8);
            cs[nt][j] += __shfl_xor_sync(0xffffffffu, cs[nt][j], 16);
        }
    if (gid == 0) {
        #pragma unroll
        for (int nt = 0; nt < 4; nt++) {
            cpart[wm][wn*32 + nt*8 + 2*tig    ] = cs[nt][0];
            cpart[wm][wn*32 + nt*8 + 2*tig + 1] = cs[nt][1];
        }
    }
    __syncthreads();
    if (tid < 64) {
        float s = cpart[0][tid] + cpart[1][tid] + cpart[2][tid] + cpart[3][tid];
        g_rcolsum[bh * Ss + bk + tid] = 1.0f / s;
    }
}

// ---------------- V' = r * V (fold softmax normalizer into V once) -----------
__global__ void __launch_bounds__(256)
vscale_kernel()
{
    int idx = blockIdx.x * 256 + threadIdx.x;
    float4* vp = (float4*)g_vproj;
    int row = idx >> 4;
    float r = g_rcolsum[row];
    float4 v = vp[idx];
    v.x *= r; v.y *= r; v.z *= r; v.w *= r;
    vp[idx] = v;
}

// ---------------- fused attention: 128q block, E stays in registers ----------
#define KST 76
#define VST 72
#define VOFF (32*KST)
#define STG  (32*KST + 32*VST)
__global__ void __launch_bounds__(256)
attn_kernel()
{
    __shared__ float KV[2][STG];
    const int bh = blockIdx.y;
    const int bq = blockIdx.x * 128;
    const int tid = threadIdx.x;
    const int lane = tid & 31, wid = tid >> 5;
    const int gid = lane >> 2, tig = lane & 3;
    const float* Qp = g_qrope + (((size_t)bh * Ss + bq) << 6);
    const float* Kp = g_kproj + ((size_t)bh * Ss << 6);
    const float* Vp = g_vproj + ((size_t)bh * Ss << 6);

    auto issueKV = [&](int s, int k0){
        #pragma unroll
        for (int l = 0; l < 4; l++) {
            int id = tid + l*256;
            int r = id >> 4, kc = (id & 15) << 2;
            if (r < 32)
                cp16(&KV[s][r*KST + kc], Kp + ((size_t)(k0 + r) << 6) + kc);
            else
                cp16(&KV[s][VOFF + (r-32)*VST + kc], Vp + ((size_t)(k0 + r - 32) << 6) + kc);
        }
    };

    float* Qst = &KV[0][0];
    #pragma unroll
    for (int l = 0; l < 8; l++) {
        int id = tid + l*256;
        int r = id >> 4, kc = (id & 15) << 2;
        cp16(&Qst[r*72 + kc], Qp + ((size_t)r << 6) + kc);
    }
    CP_COMMIT();
    CP_WAIT0();
    __syncthreads();
    const int rq = wid*16 + gid;
    unsigned aq[8][4];
    #pragma unroll
    for (int ks8 = 0; ks8 < 8; ks8++) {
        aq[ks8][0] = f2tf(Qst[ rq     *72 + ks8*8 + tig    ]);
        aq[ks8][1] = f2tf(Qst[(rq + 8)*72 + ks8*8 + tig    ]);
        aq[ks8][2] = f2tf(Qst[ rq     *72 + ks8*8 + tig + 4]);
        aq[ks8][3] = f2tf(Qst[(rq + 8)*72 + ks8*8 + tig + 4]);
    }
    __syncthreads();
    issueKV(0, 0);  CP_COMMIT();
    issueKV(1, 32); CP_COMMIT();

    float oacc[8][4];
    #pragma unroll
    for (int nt = 0; nt < 8; nt++)
        #pragma unroll
        for (int c = 0; c < 4; c++) oacc[nt][c] = 0.f;

    const int src0 = (lane & 0x1C) | (tig >> 1);
    const int src1 = src0 + 2;
    const bool podd = (tig & 1);

    for (int it = 0; it < 64; it++) {
        if (it + 1 < 64) { CP_WAIT1(); } else { CP_WAIT0(); }
        __syncthreads();
        const int s = it & 1;
        float sacc[4][4];
        #pragma unroll
        for (int nt = 0; nt < 4; nt++)
            #pragma unroll
            for (int c = 0; c < 4; c++) sacc[nt][c] = 0.f;
        #pragma unroll
        for (int ks8 = 0; ks8 < 8; ks8++) {
            unsigned bf[4][2];
            #pragma unroll
            for (int nt = 0; nt < 4; nt++) {
                int rk = nt*8 + gid;
                bf[nt][0] = f2tf(KV[s][rk*KST + ks8*8 + tig    ]);
                bf[nt][1] = f2tf(KV[s][rk*KST + ks8*8 + tig + 4]);
            }
            #pragma unroll
            for (int nt = 0; nt < 4; nt++) mma8(sacc[nt], aq[ks8], bf[nt]);
        }
        {
            int gq = bq + rq;
            #pragma unroll
            for (int nt = 0; nt < 4; nt++) {
                int gk = it*32 + nt*8 + 2*tig;
                sacc[nt][0] = (gq   == gk  ) ? 1.f : __expf(sacc[nt][0]*0.125f);
                sacc[nt][1] = (gq   == gk+1) ? 1.f : __expf(sacc[nt][1]*0.125f);
                sacc[nt][2] = (gq+8 == gk  ) ? 1.f : __expf(sacc[nt][2]*0.125f);
                sacc[nt][3] = (gq+8 == gk+1) ? 1.f : __expf(sacc[nt][3]*0.125f);
            }
        }
        const float* Vb = &KV[s][VOFF];
        #pragma unroll
        for (int ks8 = 0; ks8 < 4; ks8++) {
            float va = __shfl_sync(0xffffffffu, sacc[ks8][0], src0);
            float vb = __shfl_sync(0xffffffffu, sacc[ks8][1], src0);
            float vc = __shfl_sync(0xffffffffu, sacc[ks8][2], src0);
            float vd = __shfl_sync(0xffffffffu, sacc[ks8][3], src0);
            float wa = __shfl_sync(0xffffffffu, sacc[ks8][0], src1);
            float wb = __shfl_sync(0xffffffffu, sacc[ks8][1], src1);
            float wc = __shfl_sync(0xffffffffu, sacc[ks8][2], src1);
            float wd = __shfl_sync(0xffffffffu, sacc[ks8][3], src1);
            unsigned ae[4];
            ae[0] = f2tf(podd ? vb : va);
            ae[1] = f2tf(podd ? vd : vc);
            ae[2] = f2tf(podd ? wb : wa);
            ae[3] = f2tf(podd ? wd : wc);
            int kr0 = ks8*8 + tig, kr1 = kr0 + 4;
            #pragma unroll
            for (int nt = 0; nt < 8; nt++) {
                unsigned bv[2];
                int cd = nt*8 + gid;
                bv[0] = f2tf(Vb[kr0*VST + cd]);
                bv[1] = f2tf(Vb[kr1*VST + cd]);
                mma8(oacc[nt], ae, bv);
            }
        }
        __syncthreads();
        if (it + 2 < 64) issueKV(s, (it + 2) * 32);
        CP_COMMIT();
    }
    {
        int gq = bq + rq;
        float* O0 = g_attout + (((size_t)bh * Ss + gq) << 6);
        float* O1 = O0 + ((size_t)8 << 6);
        #pragma unroll
        for (int nt = 0; nt < 8; nt++) {
            int d = nt*8 + 2*tig;
            *(float2*)(O0 + d) = make_float2(oacc[nt][0], oacc[nt][1]);
            *(float2*)(O1 + d) = make_float2(oacc[nt][2], oacc[nt][3]);
        }
    }
}

// ---------------- launch (pure kernel launches; graph-capturable) -------------
extern "C" void kernel_launch(void* const* d_in, const int* in_sizes, int n_in,
                              void* d_out, int out_size)
{
    const float* query = (const float*)d_in[0];
    const float* key_  = (const float*)d_in[1];
    const float* value = (const float*)d_in[2];
    const int*   pos   = (const int*)  d_in[3];
    const float* Wk = (const float*)d_in[4];
    const float* bk = (const float*)d_in[5];
    const float* Wv = (const float*)d_in[6];
    const float* bv = (const float*)d_in[7];
    const float* Wo = (const float*)d_in[8];
    const float* bo = (const float*)d_in[9];
    float* out = (float*)d_out;

    dim3 blk(256);
    dim3 ggrid(Dd/128, MTOK/128);     // 8 x 32

    gemm_tc<0,0><<<ggrid, blk>>>(key_,  Wk, bk, nullptr);
    gemm_tc<1,0><<<ggrid, blk>>>(value, Wv, bv, nullptr);

    int pairs = Bb*Ss*Dd/2;
    rope_kernel<0><<<(pairs + 255)/256, 256>>>(query, pos);
    rope_kernel<1><<<(pairs + 255)/256, 256>>>(query, pos);
    rope_kernel<2><<<(pairs + 255)/256, 256>>>(query, pos);

    colsum_kernel<<<dim3(Ss/64, BH), blk>>>();
    vscale_kernel<<<(Bb*Ss*Dd/4)/256, blk>>>();
    attn_kernel<<<dim3(Ss/128, BH), blk>>>();

    gemm_tc<2,1><<<ggrid, blk>>>(nullptr, Wo, bo, out);
}